// round 2
// baseline (speedup 1.0000x reference)
#include <cuda_runtime.h>
#include <math.h>

#define NN      100000
#define EE      800000
#define IN_DIM  128
#define HID     256
#define OUT_DIM 256
#define GG      2048

#define SCAN_BLK 1024
#define NB_SCAN  ((NN + SCAN_BLK - 1) / SCAN_BLK)   // 98

// ---------------- scratch (device globals; no allocation allowed) -----------
__device__ float g_bufA[(size_t)NN * HID];   // GEMM output / agg input
__device__ float g_bufB[(size_t)NN * HID];   // agg output / next GEMM input
__device__ float g_dis[NN];
__device__ int   g_deg[NN];
__device__ int   g_rowptr[NN + 1];
__device__ int   g_cursor[NN];
__device__ int   g_csrc[EE];
__device__ float g_cnorm[EE];
__device__ float g_pool[GG * OUT_DIM];
__device__ int   g_cnt[GG];
__device__ int   g_bsum[NB_SCAN];

// ---------------- graph-structure kernels (run once per launch) -------------
__global__ void k_zero_deg() {
    int i = blockIdx.x * blockDim.x + threadIdx.x;
    if (i < NN) g_deg[i] = 0;
}

// NOTE: edge_index / batch are INT32 (JAX default x64-disabled downcasts int64)
__global__ void k_hist(const int* __restrict__ ei) {
    int e = blockIdx.x * blockDim.x + threadIdx.x;
    if (e < EE) {
        int d = ei[EE + e];                 // edge_index[1][e]
        atomicAdd(&g_deg[d], 1);
    }
}

__global__ void k_dis() {
    int i = blockIdx.x * blockDim.x + threadIdx.x;
    if (i < NN) g_dis[i] = rsqrtf((float)(g_deg[i] + 1));  // +1 self loop
}

// exclusive scan of g_deg into g_rowptr, 3 phases
__global__ void k_scan1() {
    __shared__ int s[SCAN_BLK];
    int tid = threadIdx.x;
    int i = blockIdx.x * SCAN_BLK + tid;
    int v = (i < NN) ? g_deg[i] : 0;
    s[tid] = v;
    __syncthreads();
    for (int off = 1; off < SCAN_BLK; off <<= 1) {
        int t = (tid >= off) ? s[tid - off] : 0;
        __syncthreads();
        s[tid] += t;
        __syncthreads();
    }
    if (i < NN) g_rowptr[i] = s[tid] - v;     // exclusive within block
    if (tid == SCAN_BLK - 1) g_bsum[blockIdx.x] = s[tid];
}

__global__ void k_scan2() {
    if (threadIdx.x == 0) {
        int acc = 0;
        for (int b = 0; b < NB_SCAN; b++) {
            int t = g_bsum[b];
            g_bsum[b] = acc;
            acc += t;
        }
    }
}

__global__ void k_scan3() {
    int i = blockIdx.x * blockDim.x + threadIdx.x;
    if (i < NN) {
        int r = g_rowptr[i] + g_bsum[i / SCAN_BLK];
        g_rowptr[i] = r;
        g_cursor[i] = r;
    }
    if (i == 0) g_rowptr[NN] = EE;
}

__global__ void k_fill(const int* __restrict__ ei) {
    int e = blockIdx.x * blockDim.x + threadIdx.x;
    if (e < EE) {
        int s = ei[e];
        int d = ei[EE + e];
        int p = atomicAdd(&g_cursor[d], 1);
        g_csrc[p]  = s;
        g_cnorm[p] = g_dis[s] * g_dis[d];
    }
}

// ---------------- SGEMM: C[M,256] = A[M,K] @ B[K,256] ------------------------
// 128x128 block tile, BK=16, 256 threads, 8x8 per thread
__global__ void __launch_bounds__(256)
k_gemm(const float* __restrict__ A, const float* __restrict__ B,
       float* __restrict__ C, int M, int K) {
    __shared__ float As[16][132];   // transposed A tile, padded
    __shared__ float Bs[16][128];

    int tid  = threadIdx.x;
    int brow = blockIdx.y * 128;
    int bcol = blockIdx.x * 128;
    int tx = tid & 15;      // 0..15  -> cols tx*8
    int ty = tid >> 4;      // 0..15  -> rows ty*8

    float acc[8][8];
#pragma unroll
    for (int i = 0; i < 8; i++)
#pragma unroll
        for (int j = 0; j < 8; j++) acc[i][j] = 0.f;

    for (int k0 = 0; k0 < K; k0 += 16) {
        // load A tile (128 rows x 16 k), transpose into As[k][m]
#pragma unroll
        for (int l = 0; l < 2; l++) {
            int f  = tid + l * 256;           // 0..511
            int r  = f >> 2;                  // 0..127
            int c4 = (f & 3) << 2;            // 0,4,8,12
            int row = brow + r;
            float4 v = make_float4(0.f, 0.f, 0.f, 0.f);
            if (row < M)
                v = *(const float4*)(A + (size_t)row * K + k0 + c4);
            As[c4 + 0][r] = v.x;
            As[c4 + 1][r] = v.y;
            As[c4 + 2][r] = v.z;
            As[c4 + 3][r] = v.w;
        }
        // load B tile (16 k x 128 cols)
#pragma unroll
        for (int l = 0; l < 2; l++) {
            int f  = tid + l * 256;
            int r  = f >> 5;                  // 0..15
            int c4 = (f & 31) << 2;           // 0..124
            *(float4*)&Bs[r][c4] =
                *(const float4*)(B + (size_t)(k0 + r) * 256 + bcol + c4);
        }
        __syncthreads();

#pragma unroll
        for (int kk = 0; kk < 16; kk++) {
            float a[8], b[8];
            *(float4*)&a[0] = *(float4*)&As[kk][ty * 8];
            *(float4*)&a[4] = *(float4*)&As[kk][ty * 8 + 4];
            *(float4*)&b[0] = *(float4*)&Bs[kk][tx * 8];
            *(float4*)&b[4] = *(float4*)&Bs[kk][tx * 8 + 4];
#pragma unroll
            for (int i = 0; i < 8; i++)
#pragma unroll
                for (int j = 0; j < 8; j++)
                    acc[i][j] += a[i] * b[j];
        }
        __syncthreads();
    }

#pragma unroll
    for (int i = 0; i < 8; i++) {
        int row = brow + ty * 8 + i;
        if (row < M) {
            float* cr = C + (size_t)row * 256 + bcol + tx * 8;
            *(float4*)cr       = make_float4(acc[i][0], acc[i][1], acc[i][2], acc[i][3]);
            *(float4*)(cr + 4) = make_float4(acc[i][4], acc[i][5], acc[i][6], acc[i][7]);
        }
    }
}

// ---------------- aggregation: warp per node, CSR gather --------------------
__global__ void __launch_bounds__(256)
k_agg(const float* __restrict__ hw, const float* __restrict__ bias,
      float* __restrict__ out, int relu) {
    int v    = (blockIdx.x * 256 + threadIdx.x) >> 5;
    int lane = threadIdx.x & 31;
    if (v >= NN) return;

    float ds = g_dis[v];
    float ws = ds * ds;                       // self-loop weight

    const float4* rowv = (const float4*)(hw + (size_t)v * 256);
    float4 x0 = rowv[lane];
    float4 x1 = rowv[lane + 32];
    float4 a0 = make_float4(ws * x0.x, ws * x0.y, ws * x0.z, ws * x0.w);
    float4 a1 = make_float4(ws * x1.x, ws * x1.y, ws * x1.z, ws * x1.w);

    int beg = g_rowptr[v];
    int end = g_rowptr[v + 1];
    for (int i = beg; i < end; i++) {
        int   s  = g_csrc[i];
        float nm = g_cnorm[i];
        const float4* rs = (const float4*)(hw + (size_t)s * 256);
        float4 y0 = rs[lane];
        float4 y1 = rs[lane + 32];
        a0.x += nm * y0.x; a0.y += nm * y0.y; a0.z += nm * y0.z; a0.w += nm * y0.w;
        a1.x += nm * y1.x; a1.y += nm * y1.y; a1.z += nm * y1.z; a1.w += nm * y1.w;
    }

    float4 b0 = ((const float4*)bias)[lane];
    float4 b1 = ((const float4*)bias)[lane + 32];
    a0.x += b0.x; a0.y += b0.y; a0.z += b0.z; a0.w += b0.w;
    a1.x += b1.x; a1.y += b1.y; a1.z += b1.z; a1.w += b1.w;
    if (relu) {
        a0.x = fmaxf(a0.x, 0.f); a0.y = fmaxf(a0.y, 0.f);
        a0.z = fmaxf(a0.z, 0.f); a0.w = fmaxf(a0.w, 0.f);
        a1.x = fmaxf(a1.x, 0.f); a1.y = fmaxf(a1.y, 0.f);
        a1.w = fmaxf(a1.w, 0.f); a1.z = fmaxf(a1.z, 0.f);
    }
    float4* o = (float4*)(out + (size_t)v * 256);
    o[lane]      = a0;
    o[lane + 32] = a1;
}

// ---------------- global mean pool ------------------------------------------
__global__ void k_zero_pool() {
    int i = blockIdx.x * blockDim.x + threadIdx.x;
    if (i < GG * OUT_DIM) g_pool[i] = 0.f;
    if (i < GG) g_cnt[i] = 0;
}

__global__ void k_pool(const int* __restrict__ batch,
                       const float* __restrict__ h) {
    long long idx = (long long)blockIdx.x * blockDim.x + threadIdx.x;
    if (idx >= (long long)NN * 64) return;
    int v = (int)(idx >> 6);
    int c = (int)(idx & 63);
    int g = batch[v];
    float4 val = ((const float4*)(h + (size_t)v * 256))[c];
    float* p = g_pool + (size_t)g * 256 + c * 4;
    atomicAdd(p + 0, val.x);
    atomicAdd(p + 1, val.y);
    atomicAdd(p + 2, val.z);
    atomicAdd(p + 3, val.w);
    if (c == 0) atomicAdd(&g_cnt[g], 1);
}

__global__ void k_div(float* __restrict__ out) {
    int i = blockIdx.x * blockDim.x + threadIdx.x;
    if (i < GG * OUT_DIM) {
        int g = i >> 8;
        out[i] = g_pool[i] / fmaxf((float)g_cnt[g], 1.f);
    }
}

// ---------------- launch ----------------------------------------------------
extern "C" void kernel_launch(void* const* d_in, const int* in_sizes, int n_in,
                              void* d_out, int out_size) {
    const float* x     = (const float*)d_in[0];
    const float* W1    = (const float*)d_in[1];
    const float* b1    = (const float*)d_in[2];
    const float* W2    = (const float*)d_in[3];
    const float* b2    = (const float*)d_in[4];
    const float* W3    = (const float*)d_in[5];
    const float* b3    = (const float*)d_in[6];
    const int*   ei    = (const int*)d_in[7];
    const int*   batch = (const int*)d_in[8];
    float*       out   = (float*)d_out;

    float *bufA, *bufB;
    cudaGetSymbolAddress((void**)&bufA, g_bufA);
    cudaGetSymbolAddress((void**)&bufB, g_bufB);

    dim3 blk(256);
    int gN  = (NN + 255) / 256;
    int gE  = (EE + 255) / 256;

    // build normalization + CSR (reused across all 3 layers)
    k_zero_deg<<<gN, blk>>>();
    k_hist<<<gE, blk>>>(ei);
    k_dis<<<gN, blk>>>();
    k_scan1<<<NB_SCAN, SCAN_BLK>>>();
    k_scan2<<<1, 32>>>();
    k_scan3<<<gN, blk>>>();
    k_fill<<<gE, blk>>>(ei);

    dim3 ggrid(2, (NN + 127) / 128);
    int gAgg = (NN * 32 + 255) / 256;

    // layer 1: x @ W1 -> bufA ; agg+b1+relu -> bufB
    k_gemm<<<ggrid, 256>>>(x, W1, bufA, NN, IN_DIM);
    k_agg<<<gAgg, 256>>>(bufA, b1, bufB, 1);

    // layer 2
    k_gemm<<<ggrid, 256>>>(bufB, W2, bufA, NN, HID);
    k_agg<<<gAgg, 256>>>(bufA, b2, bufB, 1);

    // layer 3 (no relu)
    k_gemm<<<ggrid, 256>>>(bufB, W3, bufA, NN, HID);
    k_agg<<<gAgg, 256>>>(bufA, b3, bufB, 0);

    // mean pool
    int gPZ = (GG * OUT_DIM + 255) / 256;
    k_zero_pool<<<gPZ, blk>>>();
    k_pool<<<(NN * 64 + 255) / 256, blk>>>(batch, bufB);
    k_div<<<gPZ, blk>>>(out);
}

// round 3
// speedup vs baseline: 1.7441x; 1.7441x over previous
#include <cuda_runtime.h>
#include <math.h>
#include <stdint.h>

#define NN      100000
#define EE      800000
#define IN_DIM  128
#define HID     256
#define OUT_DIM 256
#define GG      2048

#define SCAN_BLK 1024
#define NB_SCAN  ((NN + SCAN_BLK - 1) / SCAN_BLK)   // 98

// ---------------- scratch (device globals; no allocation allowed) -----------
__device__ float g_bufA[(size_t)NN * HID];   // GEMM output / agg input
__device__ float g_bufB[(size_t)NN * HID];   // agg output / next GEMM input
__device__ float g_dis[NN];
__device__ int   g_deg[NN];
__device__ int   g_rowptr[NN + 1];
__device__ int   g_cursor[NN];
__device__ int   g_csrc[EE];
__device__ float g_cnorm[EE];
__device__ int   g_bsum[NB_SCAN];

// ---------------- graph-structure kernels (run once per launch) -------------
__global__ void k_zero_deg() {
    int i = blockIdx.x * blockDim.x + threadIdx.x;
    if (i < NN) g_deg[i] = 0;
}

// edge_index / batch arrive as INT32 (JAX x64-disabled)
__global__ void k_hist(const int* __restrict__ ei) {
    int e = blockIdx.x * blockDim.x + threadIdx.x;
    if (e < EE) atomicAdd(&g_deg[ei[EE + e]], 1);
}

__global__ void k_dis() {
    int i = blockIdx.x * blockDim.x + threadIdx.x;
    if (i < NN) g_dis[i] = rsqrtf((float)(g_deg[i] + 1));  // +1 self loop
}

__global__ void k_scan1() {
    __shared__ int s[SCAN_BLK];
    int tid = threadIdx.x;
    int i = blockIdx.x * SCAN_BLK + tid;
    int v = (i < NN) ? g_deg[i] : 0;
    s[tid] = v;
    __syncthreads();
    for (int off = 1; off < SCAN_BLK; off <<= 1) {
        int t = (tid >= off) ? s[tid - off] : 0;
        __syncthreads();
        s[tid] += t;
        __syncthreads();
    }
    if (i < NN) g_rowptr[i] = s[tid] - v;
    if (tid == SCAN_BLK - 1) g_bsum[blockIdx.x] = s[tid];
}

__global__ void k_scan2() {
    if (threadIdx.x == 0) {
        int acc = 0;
        for (int b = 0; b < NB_SCAN; b++) {
            int t = g_bsum[b];
            g_bsum[b] = acc;
            acc += t;
        }
    }
}

__global__ void k_scan3() {
    int i = blockIdx.x * blockDim.x + threadIdx.x;
    if (i < NN) {
        int r = g_rowptr[i] + g_bsum[i / SCAN_BLK];
        g_rowptr[i] = r;
        g_cursor[i] = r;
    }
    if (i == 0) g_rowptr[NN] = EE;
}

__global__ void k_fill(const int* __restrict__ ei) {
    int e = blockIdx.x * blockDim.x + threadIdx.x;
    if (e < EE) {
        int s = ei[e];
        int d = ei[EE + e];
        int p = atomicAdd(&g_cursor[d], 1);
        g_csrc[p]  = s;
        g_cnorm[p] = g_dis[s] * g_dis[d];
    }
}

// ---------------- tf32 tensor-core GEMM: C[M,256] = A[M,K] @ B[K,256] -------
// 128x128 block tile, BK=16, 256 threads (8 warps), warp tile 64x32 via
// m16n8k8 tf32 mma.sync fragments.
__device__ __forceinline__ float f2tf32(float x) {
    uint32_t u;
    asm("cvt.rna.tf32.f32 %0, %1;" : "=r"(u) : "f"(x));
    return __uint_as_float(u);
}

__device__ __forceinline__ void mma_tf32(float* c, const uint32_t* a, const uint32_t* b) {
    asm volatile(
        "mma.sync.aligned.m16n8k8.row.col.f32.tf32.tf32.f32 "
        "{%0,%1,%2,%3}, {%4,%5,%6,%7}, {%8,%9}, {%0,%1,%2,%3};"
        : "+f"(c[0]), "+f"(c[1]), "+f"(c[2]), "+f"(c[3])
        : "r"(a[0]), "r"(a[1]), "r"(a[2]), "r"(a[3]), "r"(b[0]), "r"(b[1]));
}

__global__ void __launch_bounds__(256)
k_gemm_tc(const float* __restrict__ A, const float* __restrict__ B,
          float* __restrict__ C, int M, int K) {
    __shared__ float As[16][136];   // As[k][m], padded for conflict-free frags
    __shared__ float Bs[16][136];   // Bs[k][n]

    int tid  = threadIdx.x;
    int wid  = tid >> 5;
    int lane = tid & 31;
    int g    = lane >> 2;           // 0..7
    int tig  = lane & 3;            // 0..3
    int warp_m = wid & 1;           // 0..1  -> 64 rows
    int warp_n = wid >> 1;          // 0..3  -> 32 cols
    int brow = blockIdx.y * 128;
    int bcol = blockIdx.x * 128;

    float acc[4][4][4];
#pragma unroll
    for (int i = 0; i < 4; i++)
#pragma unroll
        for (int j = 0; j < 4; j++)
#pragma unroll
            for (int l = 0; l < 4; l++) acc[i][j][l] = 0.f;

    for (int k0 = 0; k0 < K; k0 += 16) {
        // A tile: 128 rows x 16 k, transposed into As[k][m], tf32-rounded
#pragma unroll
        for (int l = 0; l < 2; l++) {
            int f  = tid + l * 256;           // 0..511
            int r  = f >> 2;                  // row 0..127
            int c4 = (f & 3) << 2;            // k 0,4,8,12
            int row = brow + r;
            float4 v = make_float4(0.f, 0.f, 0.f, 0.f);
            if (row < M)
                v = *(const float4*)(A + (size_t)row * K + k0 + c4);
            As[c4 + 0][r] = f2tf32(v.x);
            As[c4 + 1][r] = f2tf32(v.y);
            As[c4 + 2][r] = f2tf32(v.z);
            As[c4 + 3][r] = f2tf32(v.w);
        }
        // B tile: 16 k x 128 n, tf32-rounded
#pragma unroll
        for (int l = 0; l < 2; l++) {
            int f  = tid + l * 256;
            int r  = f >> 5;                  // k 0..15
            int c4 = (f & 31) << 2;           // n 0..124
            float4 v = *(const float4*)(B + (size_t)(k0 + r) * 256 + bcol + c4);
            float4 w = make_float4(f2tf32(v.x), f2tf32(v.y), f2tf32(v.z), f2tf32(v.w));
            *(float4*)&Bs[r][c4] = w;
        }
        __syncthreads();

#pragma unroll
        for (int ks = 0; ks < 16; ks += 8) {
            uint32_t af[4][4], bf[4][2];
#pragma unroll
            for (int mf = 0; mf < 4; mf++) {
                int m0 = warp_m * 64 + mf * 16;
                af[mf][0] = __float_as_uint(As[ks + tig    ][m0 + g    ]);
                af[mf][1] = __float_as_uint(As[ks + tig    ][m0 + g + 8]);
                af[mf][2] = __float_as_uint(As[ks + tig + 4][m0 + g    ]);
                af[mf][3] = __float_as_uint(As[ks + tig + 4][m0 + g + 8]);
            }
#pragma unroll
            for (int nf = 0; nf < 4; nf++) {
                int n0 = warp_n * 32 + nf * 8;
                bf[nf][0] = __float_as_uint(Bs[ks + tig    ][n0 + g]);
                bf[nf][1] = __float_as_uint(Bs[ks + tig + 4][n0 + g]);
            }
#pragma unroll
            for (int mf = 0; mf < 4; mf++)
#pragma unroll
                for (int nf = 0; nf < 4; nf++)
                    mma_tf32(acc[mf][nf], af[mf], bf[nf]);
        }
        __syncthreads();
    }

    // epilogue: each mma frag -> two float2 stores
#pragma unroll
    for (int mf = 0; mf < 4; mf++) {
        int row0 = brow + warp_m * 64 + mf * 16 + g;
        int row1 = row0 + 8;
#pragma unroll
        for (int nf = 0; nf < 4; nf++) {
            int col = bcol + warp_n * 32 + nf * 8 + tig * 2;
            if (row0 < M)
                *(float2*)(C + (size_t)row0 * 256 + col) =
                    make_float2(acc[mf][nf][0], acc[mf][nf][1]);
            if (row1 < M)
                *(float2*)(C + (size_t)row1 * 256 + col) =
                    make_float2(acc[mf][nf][2], acc[mf][nf][3]);
        }
    }
}

// ---------------- aggregation: warp per node, CSR gather --------------------
__global__ void __launch_bounds__(256)
k_agg(const float* __restrict__ hw, const float* __restrict__ bias,
      float* __restrict__ out, int relu) {
    int v    = (blockIdx.x * 256 + threadIdx.x) >> 5;
    int lane = threadIdx.x & 31;
    if (v >= NN) return;

    float ds = g_dis[v];
    float ws = ds * ds;

    const float4* rowv = (const float4*)(hw + (size_t)v * 256);
    float4 x0 = rowv[lane];
    float4 x1 = rowv[lane + 32];
    float4 a0 = make_float4(ws * x0.x, ws * x0.y, ws * x0.z, ws * x0.w);
    float4 a1 = make_float4(ws * x1.x, ws * x1.y, ws * x1.z, ws * x1.w);

    int beg = g_rowptr[v];
    int end = g_rowptr[v + 1];
    for (int i = beg; i < end; i++) {
        int   s  = g_csrc[i];
        float nm = g_cnorm[i];
        const float4* rs = (const float4*)(hw + (size_t)s * 256);
        float4 y0 = rs[lane];
        float4 y1 = rs[lane + 32];
        a0.x += nm * y0.x; a0.y += nm * y0.y; a0.z += nm * y0.z; a0.w += nm * y0.w;
        a1.x += nm * y1.x; a1.y += nm * y1.y; a1.z += nm * y1.z; a1.w += nm * y1.w;
    }

    float4 b0 = ((const float4*)bias)[lane];
    float4 b1 = ((const float4*)bias)[lane + 32];
    a0.x += b0.x; a0.y += b0.y; a0.z += b0.z; a0.w += b0.w;
    a1.x += b1.x; a1.y += b1.y; a1.z += b1.z; a1.w += b1.w;
    if (relu) {
        a0.x = fmaxf(a0.x, 0.f); a0.y = fmaxf(a0.y, 0.f);
        a0.z = fmaxf(a0.z, 0.f); a0.w = fmaxf(a0.w, 0.f);
        a1.x = fmaxf(a1.x, 0.f); a1.y = fmaxf(a1.y, 0.f);
        a1.z = fmaxf(a1.z, 0.f); a1.w = fmaxf(a1.w, 0.f);
    }
    float4* o = (float4*)(out + (size_t)v * 256);
    o[lane]      = a0;
    o[lane + 32] = a1;
}

// ---------------- global mean pool: batch is SORTED -> block per graph ------
__global__ void __launch_bounds__(256)
k_pool2(const int* __restrict__ batch, const float* __restrict__ h,
        float* __restrict__ out) {
    int gph = blockIdx.x;
    __shared__ int s_lo, s_hi;
    if (threadIdx.x == 0) {
        int lo = 0, hi = NN;
        while (lo < hi) { int mid = (lo + hi) >> 1; if (batch[mid] < gph) lo = mid + 1; else hi = mid; }
        s_lo = lo;
    }
    if (threadIdx.x == 1) {
        int lo = 0, hi = NN;
        while (lo < hi) { int mid = (lo + hi) >> 1; if (batch[mid] < gph + 1) lo = mid + 1; else hi = mid; }
        s_hi = lo;
    }
    __syncthreads();
    int lo = s_lo, hi = s_hi;
    float acc = 0.f;
    for (int v = lo; v < hi; v++)
        acc += h[(size_t)v * 256 + threadIdx.x];
    out[(size_t)gph * 256 + threadIdx.x] = acc / fmaxf((float)(hi - lo), 1.f);
}

// ---------------- launch ----------------------------------------------------
extern "C" void kernel_launch(void* const* d_in, const int* in_sizes, int n_in,
                              void* d_out, int out_size) {
    const float* x     = (const float*)d_in[0];
    const float* W1    = (const float*)d_in[1];
    const float* b1    = (const float*)d_in[2];
    const float* W2    = (const float*)d_in[3];
    const float* b2    = (const float*)d_in[4];
    const float* W3    = (const float*)d_in[5];
    const float* b3    = (const float*)d_in[6];
    const int*   ei    = (const int*)d_in[7];
    const int*   batch = (const int*)d_in[8];
    float*       out   = (float*)d_out;

    float *bufA, *bufB;
    cudaGetSymbolAddress((void**)&bufA, g_bufA);
    cudaGetSymbolAddress((void**)&bufB, g_bufB);

    dim3 blk(256);
    int gN = (NN + 255) / 256;
    int gE = (EE + 255) / 256;

    // build normalization + CSR (reused across all 3 layers)
    k_zero_deg<<<gN, blk>>>();
    k_hist<<<gE, blk>>>(ei);
    k_dis<<<gN, blk>>>();
    k_scan1<<<NB_SCAN, SCAN_BLK>>>();
    k_scan2<<<1, 32>>>();
    k_scan3<<<gN, blk>>>();
    k_fill<<<gE, blk>>>(ei);

    dim3 ggrid(2, (NN + 127) / 128);
    int gAgg = (NN * 32 + 255) / 256;

    // layer 1
    k_gemm_tc<<<ggrid, 256>>>(x, W1, bufA, NN, IN_DIM);
    k_agg<<<gAgg, 256>>>(bufA, b1, bufB, 1);

    // layer 2
    k_gemm_tc<<<ggrid, 256>>>(bufB, W2, bufA, NN, HID);
    k_agg<<<gAgg, 256>>>(bufA, b2, bufB, 1);

    // layer 3 (no relu)
    k_gemm_tc<<<ggrid, 256>>>(bufB, W3, bufA, NN, HID);
    k_agg<<<gAgg, 256>>>(bufA, b3, bufB, 0);

    // mean pool (batch sorted -> contiguous ranges, no atomics)
    k_pool2<<<GG, 256>>>(batch, bufB, out);
}

// round 4
// speedup vs baseline: 2.2819x; 1.3083x over previous
#include <cuda_runtime.h>
#include <math.h>
#include <stdint.h>

#define NN      100000
#define EE      800000
#define IN_DIM  128
#define HID     256
#define OUT_DIM 256
#define GG      2048

#define SCAN_BLK 1024
#define NB_SCAN  ((NN + SCAN_BLK - 1) / SCAN_BLK)   // 98

// ---------------- scratch (device globals; no allocation allowed) -----------
__device__ float g_bufA[(size_t)NN * HID];
__device__ float g_bufB[(size_t)NN * HID];
__device__ float g_dis[NN];
__device__ int   g_deg[NN];          // zero-init at load; re-zeroed in k_fill
__device__ int   g_rowptr[NN + 1];
__device__ int   g_cursor[NN];
__device__ int   g_csrc[EE];
__device__ float g_cnorm[EE];
__device__ int   g_bsum[NB_SCAN];
__device__ float g_pool[(size_t)GG * OUT_DIM];
__device__ float g_maskf[GG];

// ---------------- graph-structure kernels (run once per launch) -------------
// edge_index / batch arrive as INT32 (JAX x64-disabled)
__global__ void k_hist(const int* __restrict__ ei) {
    int e = blockIdx.x * blockDim.x + threadIdx.x;
    if (e < EE) atomicAdd(&g_deg[ei[EE + e]], 1);
}

// scan phase 1 + dis computation (both consume g_deg)
__global__ void k_scan1() {
    __shared__ int s[SCAN_BLK];
    int tid = threadIdx.x;
    int i = blockIdx.x * SCAN_BLK + tid;
    int v = 0;
    if (i < NN) {
        v = g_deg[i];
        g_dis[i] = rsqrtf((float)(v + 1));   // +1 self loop
    }
    s[tid] = v;
    __syncthreads();
    for (int off = 1; off < SCAN_BLK; off <<= 1) {
        int t = (tid >= off) ? s[tid - off] : 0;
        __syncthreads();
        s[tid] += t;
        __syncthreads();
    }
    if (i < NN) g_rowptr[i] = s[tid] - v;
    if (tid == SCAN_BLK - 1) g_bsum[blockIdx.x] = s[tid];
}

__global__ void k_scan2() {
    if (threadIdx.x == 0) {
        int acc = 0;
        for (int b = 0; b < NB_SCAN; b++) {
            int t = g_bsum[b];
            g_bsum[b] = acc;
            acc += t;
        }
    }
}

__global__ void k_scan3() {
    int i = blockIdx.x * blockDim.x + threadIdx.x;
    if (i < NN) {
        int r = g_rowptr[i] + g_bsum[i / SCAN_BLK];
        g_rowptr[i] = r;
        g_cursor[i] = r;
    }
    if (i == 0) g_rowptr[NN] = EE;
}

// fill CSR; also re-zero g_deg (dead here) so the next graph replay is identical
__global__ void k_fill(const int* __restrict__ ei) {
    int e = blockIdx.x * blockDim.x + threadIdx.x;
    if (e < EE) {
        int s = ei[e];
        int d = ei[EE + e];
        int p = atomicAdd(&g_cursor[d], 1);
        g_csrc[p]  = s;
        g_cnorm[p] = g_dis[s] * g_dis[d];
    }
    if (e < NN) g_deg[e] = 0;
}

// ---------------- aggregation: warp per node, CSR gather, dim D -------------
template <int D>   // D in {128, 256}; D/128 float4s per lane
__global__ void __launch_bounds__(256)
k_agg(const float* __restrict__ in, float* __restrict__ out) {
    constexpr int NV = D / 128;
    int v    = (blockIdx.x * 256 + threadIdx.x) >> 5;
    int lane = threadIdx.x & 31;
    if (v >= NN) return;

    float ds = g_dis[v];
    float ws = ds * ds;                       // self-loop weight

    const float4* rowv = (const float4*)(in + (size_t)v * D);
    float4 a[NV];
#pragma unroll
    for (int j = 0; j < NV; j++) {
        float4 x = rowv[lane + 32 * j];
        a[j] = make_float4(ws * x.x, ws * x.y, ws * x.z, ws * x.w);
    }

    int beg = g_rowptr[v];
    int end = g_rowptr[v + 1];
    for (int i = beg; i < end; i++) {
        int   s  = g_csrc[i];
        float nm = g_cnorm[i];
        const float4* rs = (const float4*)(in + (size_t)s * D);
#pragma unroll
        for (int j = 0; j < NV; j++) {
            float4 y = rs[lane + 32 * j];
            a[j].x += nm * y.x; a[j].y += nm * y.y;
            a[j].z += nm * y.z; a[j].w += nm * y.w;
        }
    }

    float4* o = (float4*)(out + (size_t)v * D);
#pragma unroll
    for (int j = 0; j < NV; j++) o[lane + 32 * j] = a[j];
}

// ---------------- tf32 tensor-core GEMM with fused bias(+relu)(+mask) -------
// C[M,256] = act(A[M,K] @ B[K,256] + bias) * (MASK ? mask[row] : 1)
__device__ __forceinline__ float f2tf32(float x) {
    uint32_t u;
    asm("cvt.rna.tf32.f32 %0, %1;" : "=r"(u) : "f"(x));
    return __uint_as_float(u);
}

__device__ __forceinline__ void mma_tf32(float* c, const uint32_t* a, const uint32_t* b) {
    asm volatile(
        "mma.sync.aligned.m16n8k8.row.col.f32.tf32.tf32.f32 "
        "{%0,%1,%2,%3}, {%4,%5,%6,%7}, {%8,%9}, {%0,%1,%2,%3};"
        : "+f"(c[0]), "+f"(c[1]), "+f"(c[2]), "+f"(c[3])
        : "r"(a[0]), "r"(a[1]), "r"(a[2]), "r"(a[3]), "r"(b[0]), "r"(b[1]));
}

template <bool RELU, bool MASK>
__global__ void __launch_bounds__(256)
k_gemm_tc(const float* __restrict__ A, const float* __restrict__ B,
          const float* __restrict__ bias, const float* __restrict__ mask,
          float* __restrict__ C, int M, int K) {
    __shared__ float As[16][136];
    __shared__ float Bs[16][136];

    int tid  = threadIdx.x;
    int wid  = tid >> 5;
    int lane = tid & 31;
    int g    = lane >> 2;           // 0..7
    int tig  = lane & 3;            // 0..3
    int warp_m = wid & 1;
    int warp_n = wid >> 1;
    int brow = blockIdx.y * 128;
    int bcol = blockIdx.x * 128;

    float acc[4][4][4];
#pragma unroll
    for (int i = 0; i < 4; i++)
#pragma unroll
        for (int j = 0; j < 4; j++)
#pragma unroll
            for (int l = 0; l < 4; l++) acc[i][j][l] = 0.f;

    for (int k0 = 0; k0 < K; k0 += 16) {
#pragma unroll
        for (int l = 0; l < 2; l++) {
            int f  = tid + l * 256;
            int r  = f >> 2;
            int c4 = (f & 3) << 2;
            int row = brow + r;
            float4 v = make_float4(0.f, 0.f, 0.f, 0.f);
            if (row < M)
                v = *(const float4*)(A + (size_t)row * K + k0 + c4);
            As[c4 + 0][r] = f2tf32(v.x);
            As[c4 + 1][r] = f2tf32(v.y);
            As[c4 + 2][r] = f2tf32(v.z);
            As[c4 + 3][r] = f2tf32(v.w);
        }
#pragma unroll
        for (int l = 0; l < 2; l++) {
            int f  = tid + l * 256;
            int r  = f >> 5;
            int c4 = (f & 31) << 2;
            float4 v = *(const float4*)(B + (size_t)(k0 + r) * 256 + bcol + c4);
            *(float4*)&Bs[r][c4] =
                make_float4(f2tf32(v.x), f2tf32(v.y), f2tf32(v.z), f2tf32(v.w));
        }
        __syncthreads();

#pragma unroll
        for (int ks = 0; ks < 16; ks += 8) {
            uint32_t af[4][4], bf[4][2];
#pragma unroll
            for (int mf = 0; mf < 4; mf++) {
                int m0 = warp_m * 64 + mf * 16;
                af[mf][0] = __float_as_uint(As[ks + tig    ][m0 + g    ]);
                af[mf][1] = __float_as_uint(As[ks + tig    ][m0 + g + 8]);
                af[mf][2] = __float_as_uint(As[ks + tig + 4][m0 + g    ]);
                af[mf][3] = __float_as_uint(As[ks + tig + 4][m0 + g + 8]);
            }
#pragma unroll
            for (int nf = 0; nf < 4; nf++) {
                int n0 = warp_n * 32 + nf * 8;
                bf[nf][0] = __float_as_uint(Bs[ks + tig    ][n0 + g]);
                bf[nf][1] = __float_as_uint(Bs[ks + tig + 4][n0 + g]);
            }
#pragma unroll
            for (int mf = 0; mf < 4; mf++)
#pragma unroll
                for (int nf = 0; nf < 4; nf++)
                    mma_tf32(acc[mf][nf], af[mf], bf[nf]);
        }
        __syncthreads();
    }

#pragma unroll
    for (int mf = 0; mf < 4; mf++) {
        int row0 = brow + warp_m * 64 + mf * 16 + g;
        int row1 = row0 + 8;
        float mk0 = 1.f, mk1 = 1.f;
        if (MASK) {
            if (row0 < M) mk0 = mask[row0];
            if (row1 < M) mk1 = mask[row1];
        }
#pragma unroll
        for (int nf = 0; nf < 4; nf++) {
            int col = bcol + warp_n * 32 + nf * 8 + tig * 2;
            float2 bb = *(const float2*)(bias + col);
            float v0 = acc[mf][nf][0] + bb.x;
            float v1 = acc[mf][nf][1] + bb.y;
            float v2 = acc[mf][nf][2] + bb.x;
            float v3 = acc[mf][nf][3] + bb.y;
            if (RELU) {
                v0 = fmaxf(v0, 0.f); v1 = fmaxf(v1, 0.f);
                v2 = fmaxf(v2, 0.f); v3 = fmaxf(v3, 0.f);
            }
            if (row0 < M)
                *(float2*)(C + (size_t)row0 * 256 + col) = make_float2(v0 * mk0, v1 * mk0);
            if (row1 < M)
                *(float2*)(C + (size_t)row1 * 256 + col) = make_float2(v2 * mk1, v3 * mk1);
        }
    }
}

// ---------------- global mean pool (batch sorted): block per graph ----------
__global__ void __launch_bounds__(256)
k_pool2(const int* __restrict__ batch, const float* __restrict__ h) {
    int gph = blockIdx.x;
    __shared__ int s_lo, s_hi;
    if (threadIdx.x == 0) {
        int lo = 0, hi = NN;
        while (lo < hi) { int mid = (lo + hi) >> 1; if (batch[mid] < gph) lo = mid + 1; else hi = mid; }
        s_lo = lo;
    }
    if (threadIdx.x == 1) {
        int lo = 0, hi = NN;
        while (lo < hi) { int mid = (lo + hi) >> 1; if (batch[mid] < gph + 1) lo = mid + 1; else hi = mid; }
        s_hi = lo;
    }
    __syncthreads();
    int lo = s_lo, hi = s_hi;
    float acc = 0.f;
    for (int v = lo; v < hi; v++)
        acc += h[(size_t)v * 256 + threadIdx.x];
    g_pool[(size_t)gph * 256 + threadIdx.x] = acc / fmaxf((float)(hi - lo), 1.f);
    if (threadIdx.x == 0) g_maskf[gph] = (hi > lo) ? 1.f : 0.f;
}

// ---------------- launch ----------------------------------------------------
extern "C" void kernel_launch(void* const* d_in, const int* in_sizes, int n_in,
                              void* d_out, int out_size) {
    const float* x     = (const float*)d_in[0];
    const float* W1    = (const float*)d_in[1];
    const float* b1    = (const float*)d_in[2];
    const float* W2    = (const float*)d_in[3];
    const float* b2    = (const float*)d_in[4];
    const float* W3    = (const float*)d_in[5];
    const float* b3    = (const float*)d_in[6];
    const int*   ei    = (const int*)d_in[7];
    const int*   batch = (const int*)d_in[8];
    float*       out   = (float*)d_out;

    float *bufA, *bufB, *poolb, *maskb;
    cudaGetSymbolAddress((void**)&bufA, g_bufA);
    cudaGetSymbolAddress((void**)&bufB, g_bufB);
    cudaGetSymbolAddress((void**)&poolb, g_pool);
    cudaGetSymbolAddress((void**)&maskb, g_maskf);

    dim3 blk(256);
    int gN = (NN + 255) / 256;
    int gE = (EE + 255) / 256;

    // CSR build (5 launches; ncu -s 5 then lands on k_agg<128>)
    k_hist<<<gE, blk>>>(ei);
    k_scan1<<<NB_SCAN, SCAN_BLK>>>();
    k_scan2<<<1, 32>>>();
    k_scan3<<<gN, blk>>>();
    k_fill<<<gE, blk>>>(ei);

    dim3 ggrid(2, (NN + 127) / 128);
    dim3 ggrid3(2, GG / 128);
    int gAgg = (NN * 32 + 255) / 256;

    // layer 1: agg in 128-dim, then GEMM(+bias+relu)
    k_agg<128><<<gAgg, 256>>>(x, bufA);
    k_gemm_tc<true, false><<<ggrid, 256>>>(bufA, W1, b1, nullptr, bufB, NN, IN_DIM);

    // layer 2
    k_agg<256><<<gAgg, 256>>>(bufB, bufA);
    k_gemm_tc<true, false><<<ggrid, 256>>>(bufA, W2, b2, nullptr, bufB, NN, HID);

    // layer 3: agg, pool (linear), then tiny GEMM on pooled [G,256]
    k_agg<256><<<gAgg, 256>>>(bufB, bufA);
    k_pool2<<<GG, 256>>>(batch, bufA);
    k_gemm_tc<false, true><<<ggrid3, 256>>>(poolb, W3, b3, maskb, out, GG, HID);
}

// round 5
// speedup vs baseline: 2.5423x; 1.1141x over previous
#include <cuda_runtime.h>
#include <math.h>
#include <stdint.h>

#define NN      100000
#define EE      800000
#define IN_DIM  128
#define HID     256
#define OUT_DIM 256
#define GG      2048

#define SCAN_BLK 1024
#define NB_SCAN  ((NN + SCAN_BLK - 1) / SCAN_BLK)   // 98

// ---------------- scratch (device globals; no allocation allowed) -----------
__device__ float g_bufA[(size_t)NN * HID];
__device__ float g_bufB[(size_t)NN * HID];
__device__ float g_dis[NN];
__device__ int   g_deg[NN];          // zero-init at load; re-zeroed in k_fill
__device__ int   g_rowptr[NN + 1];
__device__ int   g_cursor[NN];
__device__ int   g_csrc[EE];
__device__ float g_cnorm[EE];
__device__ int   g_bsum[NB_SCAN];
__device__ float g_pool[(size_t)GG * OUT_DIM];
__device__ float g_maskf[GG];

// ---------------- helpers ---------------------------------------------------
__device__ __forceinline__ float f2tf32(float x) {
    uint32_t u;
    asm("cvt.rna.tf32.f32 %0, %1;" : "=r"(u) : "f"(x));
    return __uint_as_float(u);
}

__device__ __forceinline__ uint32_t smem_u32(const void* p) {
    uint32_t a;
    asm("{ .reg .u64 t; cvta.to.shared.u64 t, %1; cvt.u32.u64 %0, t; }"
        : "=r"(a) : "l"(p));
    return a;
}

__device__ __forceinline__ void cp16(uint32_t dst, const void* src, int src_sz) {
    asm volatile("cp.async.cg.shared.global [%0], [%1], 16, %2;"
                 :: "r"(dst), "l"(src), "r"(src_sz));
}

__device__ __forceinline__ void mma_tf32(float* c, const uint32_t* a, const uint32_t* b) {
    asm volatile(
        "mma.sync.aligned.m16n8k8.row.col.f32.tf32.tf32.f32 "
        "{%0,%1,%2,%3}, {%4,%5,%6,%7}, {%8,%9}, {%0,%1,%2,%3};"
        : "+f"(c[0]), "+f"(c[1]), "+f"(c[2]), "+f"(c[3])
        : "r"(a[0]), "r"(a[1]), "r"(a[2]), "r"(a[3]), "r"(b[0]), "r"(b[1]));
}

// ---------------- graph-structure kernels (run once per launch) -------------
// edge_index / batch arrive as INT32 (JAX x64-disabled)
__global__ void k_hist(const int* __restrict__ ei) {
    int e = blockIdx.x * blockDim.x + threadIdx.x;
    if (e < EE) atomicAdd(&g_deg[ei[EE + e]], 1);
}

__global__ void k_scan1() {
    __shared__ int s[SCAN_BLK];
    int tid = threadIdx.x;
    int i = blockIdx.x * SCAN_BLK + tid;
    int v = 0;
    if (i < NN) {
        v = g_deg[i];
        g_dis[i] = rsqrtf((float)(v + 1));   // +1 self loop
    }
    s[tid] = v;
    __syncthreads();
    for (int off = 1; off < SCAN_BLK; off <<= 1) {
        int t = (tid >= off) ? s[tid - off] : 0;
        __syncthreads();
        s[tid] += t;
        __syncthreads();
    }
    if (i < NN) g_rowptr[i] = s[tid] - v;
    if (tid == SCAN_BLK - 1) g_bsum[blockIdx.x] = s[tid];
}

__global__ void k_scan2() {
    if (threadIdx.x == 0) {
        int acc = 0;
        for (int b = 0; b < NB_SCAN; b++) {
            int t = g_bsum[b];
            g_bsum[b] = acc;
            acc += t;
        }
    }
}

__global__ void k_scan3() {
    int i = blockIdx.x * blockDim.x + threadIdx.x;
    if (i < NN) {
        int r = g_rowptr[i] + g_bsum[i / SCAN_BLK];
        g_rowptr[i] = r;
        g_cursor[i] = r;
    }
    if (i == 0) g_rowptr[NN] = EE;
}

// fill CSR; also re-zero g_deg (dead here) so the next graph replay is identical
__global__ void k_fill(const int* __restrict__ ei) {
    int e = blockIdx.x * blockDim.x + threadIdx.x;
    if (e < EE) {
        int s = ei[e];
        int d = ei[EE + e];
        int p = atomicAdd(&g_cursor[d], 1);
        g_csrc[p]  = s;
        g_cnorm[p] = g_dis[s] * g_dis[d];
    }
    if (e < NN) g_deg[e] = 0;
}

// ---------------- aggregation: warp per node, CSR gather, dim D -------------
// Output is tf32-rounded (consumed only by the tf32 GEMM).
template <int D>   // D in {128, 256}
__global__ void __launch_bounds__(256)
k_agg(const float* __restrict__ in, float* __restrict__ out) {
    constexpr int NV = D / 128;
    int v    = (blockIdx.x * 256 + threadIdx.x) >> 5;
    int lane = threadIdx.x & 31;
    if (v >= NN) return;

    float ds = g_dis[v];
    float ws = ds * ds;                       // self-loop weight

    const float4* rowv = (const float4*)(in + (size_t)v * D);
    float4 a[NV];
#pragma unroll
    for (int j = 0; j < NV; j++) {
        float4 x = rowv[lane + 32 * j];
        a[j] = make_float4(ws * x.x, ws * x.y, ws * x.z, ws * x.w);
    }

    int beg = g_rowptr[v];
    int end = g_rowptr[v + 1];
    int i = beg;
    for (; i + 1 < end; i += 2) {
        int   s0 = g_csrc[i],     s1 = g_csrc[i + 1];
        float n0 = g_cnorm[i],    n1 = g_cnorm[i + 1];
        const float4* r0 = (const float4*)(in + (size_t)s0 * D);
        const float4* r1 = (const float4*)(in + (size_t)s1 * D);
#pragma unroll
        for (int j = 0; j < NV; j++) {
            float4 y0 = r0[lane + 32 * j];
            float4 y1 = r1[lane + 32 * j];
            a[j].x += n0 * y0.x + n1 * y1.x;
            a[j].y += n0 * y0.y + n1 * y1.y;
            a[j].z += n0 * y0.z + n1 * y1.z;
            a[j].w += n0 * y0.w + n1 * y1.w;
        }
    }
    if (i < end) {
        int   s0 = g_csrc[i];
        float n0 = g_cnorm[i];
        const float4* r0 = (const float4*)(in + (size_t)s0 * D);
#pragma unroll
        for (int j = 0; j < NV; j++) {
            float4 y0 = r0[lane + 32 * j];
            a[j].x += n0 * y0.x; a[j].y += n0 * y0.y;
            a[j].z += n0 * y0.z; a[j].w += n0 * y0.w;
        }
    }

    float4* o = (float4*)(out + (size_t)v * D);
#pragma unroll
    for (int j = 0; j < NV; j++)
        o[lane + 32 * j] = make_float4(f2tf32(a[j].x), f2tf32(a[j].y),
                                       f2tf32(a[j].z), f2tf32(a[j].w));
}

// ---------------- tf32 tensor-core GEMM, cp.async double-buffered -----------
// C[M,256] = act(A[M,K] @ B[K,256] + bias) * (MASK ? mask[row] : 1)
// A must already be tf32-rounded; B (weights) is cvt'd in registers.
template <bool RELU, bool MASK>
__global__ void __launch_bounds__(256, 2)
k_gemm_tc(const float* __restrict__ A, const float* __restrict__ B,
          const float* __restrict__ bias, const float* __restrict__ mask,
          float* __restrict__ C, int M, int K) {
    __shared__ float As[2][128][20];   // row-major A tile, pad->conflict-free frags
    __shared__ float Bs[2][16][136];

    int tid  = threadIdx.x;
    int wid  = tid >> 5;
    int lane = tid & 31;
    int g    = lane >> 2;           // 0..7
    int tig  = lane & 3;            // 0..3
    int warp_m = wid & 1;
    int warp_n = wid >> 1;
    int brow = blockIdx.y * 128;
    int bcol = blockIdx.x * 128;

    float acc[4][4][4];
#pragma unroll
    for (int i = 0; i < 4; i++)
#pragma unroll
        for (int j = 0; j < 4; j++)
#pragma unroll
            for (int l = 0; l < 4; l++) acc[i][j][l] = 0.f;

    // precomputed per-thread load slots
    int ar  = tid >> 2;             // A row within tile (0..63, +64 for l=1)
    int ac4 = (tid & 3) << 2;       // A k-offset 0,4,8,12
    int br  = tid >> 5;             // B k-row (0..7, +8 for l=1)
    int bc4 = (tid & 31) << 2;      // B n-offset

    auto load_tiles = [&](int s, int k0) {
#pragma unroll
        for (int l = 0; l < 2; l++) {
            int r   = ar + l * 64;
            int row = brow + r;
            cp16(smem_u32(&As[s][r][ac4]),
                 A + (size_t)row * K + k0 + ac4, row < M ? 16 : 0);
        }
#pragma unroll
        for (int l = 0; l < 2; l++) {
            int r = br + l * 8;
            cp16(smem_u32(&Bs[s][r][bc4]),
                 B + (size_t)(k0 + r) * 256 + bcol + bc4, 16);
        }
        asm volatile("cp.async.commit_group;");
    };

    load_tiles(0, 0);
    int s = 0;
    for (int k0 = 0; k0 < K; k0 += 16) {
        if (k0 + 16 < K) load_tiles(s ^ 1, k0 + 16);
        else             asm volatile("cp.async.commit_group;");
        asm volatile("cp.async.wait_group 1;");
        __syncthreads();

#pragma unroll
        for (int ks = 0; ks < 16; ks += 8) {
            uint32_t af[4][4], bf[4][2];
#pragma unroll
            for (int mf = 0; mf < 4; mf++) {
                int m0 = warp_m * 64 + mf * 16;
                af[mf][0] = __float_as_uint(As[s][m0 + g    ][ks + tig    ]);
                af[mf][1] = __float_as_uint(As[s][m0 + g + 8][ks + tig    ]);
                af[mf][2] = __float_as_uint(As[s][m0 + g    ][ks + tig + 4]);
                af[mf][3] = __float_as_uint(As[s][m0 + g + 8][ks + tig + 4]);
            }
#pragma unroll
            for (int nf = 0; nf < 4; nf++) {
                int n0 = warp_n * 32 + nf * 8;
                bf[nf][0] = __float_as_uint(f2tf32(Bs[s][ks + tig    ][n0 + g]));
                bf[nf][1] = __float_as_uint(f2tf32(Bs[s][ks + tig + 4][n0 + g]));
            }
#pragma unroll
            for (int mf = 0; mf < 4; mf++)
#pragma unroll
                for (int nf = 0; nf < 4; nf++)
                    mma_tf32(acc[mf][nf], af[mf], bf[nf]);
        }
        __syncthreads();
        s ^= 1;
    }

#pragma unroll
    for (int mf = 0; mf < 4; mf++) {
        int row0 = brow + warp_m * 64 + mf * 16 + g;
        int row1 = row0 + 8;
        float mk0 = 1.f, mk1 = 1.f;
        if (MASK) {
            if (row0 < M) mk0 = mask[row0];
            if (row1 < M) mk1 = mask[row1];
        }
#pragma unroll
        for (int nf = 0; nf < 4; nf++) {
            int col = bcol + warp_n * 32 + nf * 8 + tig * 2;
            float2 bb = *(const float2*)(bias + col);
            float v0 = acc[mf][nf][0] + bb.x;
            float v1 = acc[mf][nf][1] + bb.y;
            float v2 = acc[mf][nf][2] + bb.x;
            float v3 = acc[mf][nf][3] + bb.y;
            if (RELU) {
                v0 = fmaxf(v0, 0.f); v1 = fmaxf(v1, 0.f);
                v2 = fmaxf(v2, 0.f); v3 = fmaxf(v3, 0.f);
            }
            if (row0 < M)
                *(float2*)(C + (size_t)row0 * 256 + col) = make_float2(v0 * mk0, v1 * mk0);
            if (row1 < M)
                *(float2*)(C + (size_t)row1 * 256 + col) = make_float2(v2 * mk1, v3 * mk1);
        }
    }
}

// ---------------- global mean pool (batch sorted): block per graph ----------
// Output tf32-rounded (feeds the tf32 GEMM3).
__global__ void __launch_bounds__(256)
k_pool2(const int* __restrict__ batch, const float* __restrict__ h) {
    int gph = blockIdx.x;
    __shared__ int s_lo, s_hi;
    if (threadIdx.x == 0) {
        int lo = 0, hi = NN;
        while (lo < hi) { int mid = (lo + hi) >> 1; if (batch[mid] < gph) lo = mid + 1; else hi = mid; }
        s_lo = lo;
    }
    if (threadIdx.x == 1) {
        int lo = 0, hi = NN;
        while (lo < hi) { int mid = (lo + hi) >> 1; if (batch[mid] < gph + 1) lo = mid + 1; else hi = mid; }
        s_hi = lo;
    }
    __syncthreads();
    int lo = s_lo, hi = s_hi;
    float acc = 0.f;
    for (int v = lo; v < hi; v++)
        acc += h[(size_t)v * 256 + threadIdx.x];
    g_pool[(size_t)gph * 256 + threadIdx.x] =
        f2tf32(acc / fmaxf((float)(hi - lo), 1.f));
    if (threadIdx.x == 0) g_maskf[gph] = (hi > lo) ? 1.f : 0.f;
}

// ---------------- launch ----------------------------------------------------
extern "C" void kernel_launch(void* const* d_in, const int* in_sizes, int n_in,
                              void* d_out, int out_size) {
    const float* x     = (const float*)d_in[0];
    const float* W1    = (const float*)d_in[1];
    const float* b1    = (const float*)d_in[2];
    const float* W2    = (const float*)d_in[3];
    const float* b2    = (const float*)d_in[4];
    const float* W3    = (const float*)d_in[5];
    const float* b3    = (const float*)d_in[6];
    const int*   ei    = (const int*)d_in[7];
    const int*   batch = (const int*)d_in[8];
    float*       out   = (float*)d_out;

    float *bufA, *bufB, *poolb, *maskb;
    cudaGetSymbolAddress((void**)&bufA, g_bufA);
    cudaGetSymbolAddress((void**)&bufB, g_bufB);
    cudaGetSymbolAddress((void**)&poolb, g_pool);
    cudaGetSymbolAddress((void**)&maskb, g_maskf);

    dim3 blk(256);
    int gN = (NN + 255) / 256;
    int gE = (EE + 255) / 256;

    // CSR build
    k_hist<<<gE, blk>>>(ei);
    k_scan1<<<NB_SCAN, SCAN_BLK>>>();
    k_scan2<<<1, 32>>>();
    k_scan3<<<gN, blk>>>();
    k_fill<<<gE, blk>>>(ei);

    dim3 ggrid(2, (NN + 127) / 128);
    dim3 ggrid3(2, GG / 128);
    int gAgg = (NN * 32 + 255) / 256;

    // layer 1: agg in 128-dim, then GEMM(+bias+relu)
    k_agg<128><<<gAgg, 256>>>(x, bufA);
    k_gemm_tc<true, false><<<ggrid, 256>>>(bufA, W1, b1, nullptr, bufB, NN, IN_DIM);

    // layer 2
    k_agg<256><<<gAgg, 256>>>(bufB, bufA);
    k_gemm_tc<true, false><<<ggrid, 256>>>(bufA, W2, b2, nullptr, bufB, NN, HID);

    // layer 3: agg, pool (linear), then tiny GEMM on pooled [G,256]
    k_agg<256><<<gAgg, 256>>>(bufB, bufA);
    k_pool2<<<GG, 256>>>(batch, bufA);
    k_gemm_tc<false, true><<<ggrid3, 256>>>(poolb, W3, b3, maskb, out, GG, HID);
}

// round 6
// speedup vs baseline: 3.5505x; 1.3966x over previous
#include <cuda_runtime.h>
#include <cuda_fp16.h>
#include <math.h>
#include <stdint.h>

#define NN      100000
#define EE      800000
#define IN_DIM  128
#define HID     256
#define OUT_DIM 256
#define GG      2048

#define SCAN_BLK 1024
#define NB_SCAN  ((NN + SCAN_BLK - 1) / SCAN_BLK)   // 98

// ---------------- scratch (device globals; no allocation allowed) -----------
__device__ __half g_bufAh[(size_t)NN * HID];
__device__ __half g_bufBh[(size_t)NN * HID];
__device__ __half g_xh[(size_t)NN * IN_DIM];
__device__ __half g_w1h[256 * IN_DIM];    // [n][k] transposed
__device__ __half g_w2h[256 * HID];
__device__ __half g_w3h[256 * HID];
__device__ __half g_poolh[(size_t)GG * OUT_DIM];
__device__ float  g_dis[NN];
__device__ int    g_deg[NN];         // zero-init at load; re-zeroed in k_fill
__device__ int    g_rowptr[NN + 1];
__device__ int    g_cursor[NN];
__device__ int    g_csrc[EE];
__device__ float  g_cnorm[EE];
__device__ int    g_bsum[NB_SCAN];
__device__ float  g_maskf[GG];

// ---------------- helpers ---------------------------------------------------
__device__ __forceinline__ uint32_t smem_u32(const void* p) {
    uint32_t a;
    asm("{ .reg .u64 t; cvta.to.shared.u64 t, %1; cvt.u32.u64 %0, t; }"
        : "=r"(a) : "l"(p));
    return a;
}

__device__ __forceinline__ void cp16(uint32_t dst, const void* src, int src_sz) {
    asm volatile("cp.async.cg.shared.global [%0], [%1], 16, %2;"
                 :: "r"(dst), "l"(src), "r"(src_sz));
}

__device__ __forceinline__ void mma_f16(float* c, const uint32_t* a, const uint32_t* b) {
    asm volatile(
        "mma.sync.aligned.m16n8k16.row.col.f32.f16.f16.f32 "
        "{%0,%1,%2,%3}, {%4,%5,%6,%7}, {%8,%9}, {%0,%1,%2,%3};"
        : "+f"(c[0]), "+f"(c[1]), "+f"(c[2]), "+f"(c[3])
        : "r"(a[0]), "r"(a[1]), "r"(a[2]), "r"(a[3]), "r"(b[0]), "r"(b[1]));
}

// ---------------- conversions (once per launch) -----------------------------
// W[K][256] float -> Wt[256][K] half
__global__ void k_cvt_w(const float* __restrict__ W, __half* __restrict__ Wt, int K) {
    int idx = blockIdx.x * blockDim.x + threadIdx.x;
    if (idx < 256 * K) {
        int n = idx / K, k = idx - n * K;
        Wt[idx] = __float2half(W[(size_t)k * 256 + n]);
    }
}

__global__ void k_cvt_x(const float* __restrict__ x) {
    int i = blockIdx.x * blockDim.x + threadIdx.x;
    if (i < NN * IN_DIM / 4) {
        float4 v = ((const float4*)x)[i];
        __half2 h0 = __floats2half2_rn(v.x, v.y);
        __half2 h1 = __floats2half2_rn(v.z, v.w);
        uint2 u;
        u.x = *(uint32_t*)&h0;
        u.y = *(uint32_t*)&h1;
        ((uint2*)g_xh)[i] = u;
    }
}

// ---------------- graph-structure kernels -----------------------------------
// edge_index / batch arrive as INT32 (JAX x64-disabled)
__global__ void k_hist(const int* __restrict__ ei) {
    int e = blockIdx.x * blockDim.x + threadIdx.x;
    if (e < EE) atomicAdd(&g_deg[ei[EE + e]], 1);
}

__global__ void k_scan1() {
    __shared__ int s[SCAN_BLK];
    int tid = threadIdx.x;
    int i = blockIdx.x * SCAN_BLK + tid;
    int v = 0;
    if (i < NN) {
        v = g_deg[i];
        g_dis[i] = rsqrtf((float)(v + 1));   // +1 self loop
    }
    s[tid] = v;
    __syncthreads();
    for (int off = 1; off < SCAN_BLK; off <<= 1) {
        int t = (tid >= off) ? s[tid - off] : 0;
        __syncthreads();
        s[tid] += t;
        __syncthreads();
    }
    if (i < NN) g_rowptr[i] = s[tid] - v;
    if (tid == SCAN_BLK - 1) g_bsum[blockIdx.x] = s[tid];
}

__global__ void k_scan2() {
    if (threadIdx.x == 0) {
        int acc = 0;
        for (int b = 0; b < NB_SCAN; b++) {
            int t = g_bsum[b];
            g_bsum[b] = acc;
            acc += t;
        }
    }
}

__global__ void k_scan3() {
    int i = blockIdx.x * blockDim.x + threadIdx.x;
    if (i < NN) {
        int r = g_rowptr[i] + g_bsum[i / SCAN_BLK];
        g_rowptr[i] = r;
        g_cursor[i] = r;
    }
    if (i == 0) g_rowptr[NN] = EE;
}

__global__ void k_fill(const int* __restrict__ ei) {
    int e = blockIdx.x * blockDim.x + threadIdx.x;
    if (e < EE) {
        int s = ei[e];
        int d = ei[EE + e];
        int p = atomicAdd(&g_cursor[d], 1);
        g_csrc[p]  = s;
        g_cnorm[p] = g_dis[s] * g_dis[d];
    }
    if (e < NN) g_deg[e] = 0;   // re-zero for next graph replay
}

// ---------------- aggregation: warp per node, half gather, fp32 accum -------
template <int D>   // D in {128, 256}; VH = half2 per lane
__global__ void __launch_bounds__(256)
k_agg_h(const __half* __restrict__ in, __half* __restrict__ out) {
    constexpr int VH = D / 64;            // 2 or 4
    int v    = (blockIdx.x * 256 + threadIdx.x) >> 5;
    int lane = threadIdx.x & 31;
    if (v >= NN) return;

    float ds = g_dis[v];
    float ws = ds * ds;                   // self-loop weight

    const __half* rowv = in + (size_t)v * D + lane * (VH * 2);
    float2 a[VH];
#pragma unroll
    for (int j = 0; j < VH; j++) {
        __half2 h = ((const __half2*)rowv)[j];
        float2 x = __half22float2(h);
        a[j] = make_float2(ws * x.x, ws * x.y);
    }

    int beg = g_rowptr[v];
    int end = g_rowptr[v + 1];
    int i = beg;
    for (; i + 1 < end; i += 2) {
        int   s0 = g_csrc[i],  s1 = g_csrc[i + 1];
        float n0 = g_cnorm[i], n1 = g_cnorm[i + 1];
        const __half2* r0 = (const __half2*)(in + (size_t)s0 * D + lane * (VH * 2));
        const __half2* r1 = (const __half2*)(in + (size_t)s1 * D + lane * (VH * 2));
        __half2 h0[VH], h1[VH];
        if (VH == 4) {
            float4 u0 = *(const float4*)r0;
            float4 u1 = *(const float4*)r1;
            h0[0] = *(__half2*)&u0.x; h0[1] = *(__half2*)&u0.y;
            h0[2] = *(__half2*)&u0.z; h0[3] = *(__half2*)&u0.w;
            h1[0] = *(__half2*)&u1.x; h1[1] = *(__half2*)&u1.y;
            h1[2] = *(__half2*)&u1.z; h1[3] = *(__half2*)&u1.w;
        } else {
            float2 u0 = *(const float2*)r0;
            float2 u1 = *(const float2*)r1;
            h0[0] = *(__half2*)&u0.x; h0[1] = *(__half2*)&u0.y;
            h1[0] = *(__half2*)&u1.x; h1[1] = *(__half2*)&u1.y;
        }
#pragma unroll
        for (int j = 0; j < VH; j++) {
            float2 y0 = __half22float2(h0[j]);
            float2 y1 = __half22float2(h1[j]);
            a[j].x += n0 * y0.x + n1 * y1.x;
            a[j].y += n0 * y0.y + n1 * y1.y;
        }
    }
    if (i < end) {
        int   s0 = g_csrc[i];
        float n0 = g_cnorm[i];
        const __half2* r0 = (const __half2*)(in + (size_t)s0 * D + lane * (VH * 2));
#pragma unroll
        for (int j = 0; j < VH; j++) {
            float2 y0 = __half22float2(r0[j]);
            a[j].x += n0 * y0.x;
            a[j].y += n0 * y0.y;
        }
    }

    __half2* o = (__half2*)(out + (size_t)v * D + lane * (VH * 2));
#pragma unroll
    for (int j = 0; j < VH; j++)
        o[j] = __floats2half2_rn(a[j].x, a[j].y);
}

// ---------------- fp16 tensor-core GEMM, cp.async double-buffered -----------
// C[M,256] = act(A[M,K] @ Wt^T + bias) [* mask[row]]
// A: [M][K] half (row-major). Wt: [256][K] half (n-major).
template <bool RELU, bool MASK, bool HALF_OUT>
__global__ void __launch_bounds__(256, 2)
k_gemm_h(const __half* __restrict__ A, const __half* __restrict__ Wt,
         const float* __restrict__ bias, const float* __restrict__ mask,
         void* __restrict__ Cout, int M, int K) {
    __shared__ __half As[2][128][40];   // [m][k], 80B rows -> conflict-free frags
    __shared__ __half Bs[2][128][40];   // [n][k]

    int tid  = threadIdx.x;
    int wid  = tid >> 5;
    int lane = tid & 31;
    int g    = lane >> 2;           // 0..7
    int tig  = lane & 3;            // 0..3
    int warp_m = wid & 1;
    int warp_n = wid >> 1;
    int brow = blockIdx.y * 128;
    int bcol = blockIdx.x * 128;

    float acc[4][4][4];
#pragma unroll
    for (int i = 0; i < 4; i++)
#pragma unroll
        for (int j = 0; j < 4; j++)
#pragma unroll
            for (int l = 0; l < 4; l++) acc[i][j][l] = 0.f;

    int lr  = tid >> 2;             // 0..63 (+64 on l=1)
    int lc8 = (tid & 3) << 3;       // k-offset 0,8,16,24 halves

    auto load_tiles = [&](int s, int k0) {
#pragma unroll
        for (int l = 0; l < 2; l++) {
            int r = lr + l * 64;
            int row = brow + r;
            cp16(smem_u32(&As[s][r][lc8]),
                 A + (size_t)row * K + k0 + lc8, row < M ? 16 : 0);
            cp16(smem_u32(&Bs[s][r][lc8]),
                 Wt + (size_t)(bcol + r) * K + k0 + lc8, 16);
        }
        asm volatile("cp.async.commit_group;");
    };

    load_tiles(0, 0);
    int s = 0;
    for (int k0 = 0; k0 < K; k0 += 32) {
        if (k0 + 32 < K) load_tiles(s ^ 1, k0 + 32);
        else             asm volatile("cp.async.commit_group;");
        asm volatile("cp.async.wait_group 1;");
        __syncthreads();

#pragma unroll
        for (int ks = 0; ks < 32; ks += 16) {
            uint32_t af[4][4], bf[4][2];
#pragma unroll
            for (int mf = 0; mf < 4; mf++) {
                int m0 = warp_m * 64 + mf * 16;
                af[mf][0] = *(const uint32_t*)&As[s][m0 + g    ][ks + tig * 2    ];
                af[mf][1] = *(const uint32_t*)&As[s][m0 + g + 8][ks + tig * 2    ];
                af[mf][2] = *(const uint32_t*)&As[s][m0 + g    ][ks + tig * 2 + 8];
                af[mf][3] = *(const uint32_t*)&As[s][m0 + g + 8][ks + tig * 2 + 8];
            }
#pragma unroll
            for (int nf = 0; nf < 4; nf++) {
                int n0 = warp_n * 32 + nf * 8;
                bf[nf][0] = *(const uint32_t*)&Bs[s][n0 + g][ks + tig * 2    ];
                bf[nf][1] = *(const uint32_t*)&Bs[s][n0 + g][ks + tig * 2 + 8];
            }
#pragma unroll
            for (int mf = 0; mf < 4; mf++)
#pragma unroll
                for (int nf = 0; nf < 4; nf++)
                    mma_f16(acc[mf][nf], af[mf], bf[nf]);
        }
        __syncthreads();
        s ^= 1;
    }

#pragma unroll
    for (int mf = 0; mf < 4; mf++) {
        int row0 = brow + warp_m * 64 + mf * 16 + g;
        int row1 = row0 + 8;
        float mk0 = 1.f, mk1 = 1.f;
        if (MASK) {
            if (row0 < M) mk0 = mask[row0];
            if (row1 < M) mk1 = mask[row1];
        }
#pragma unroll
        for (int nf = 0; nf < 4; nf++) {
            int col = bcol + warp_n * 32 + nf * 8 + tig * 2;
            float2 bb = *(const float2*)(bias + col);
            float v0 = acc[mf][nf][0] + bb.x;
            float v1 = acc[mf][nf][1] + bb.y;
            float v2 = acc[mf][nf][2] + bb.x;
            float v3 = acc[mf][nf][3] + bb.y;
            if (RELU) {
                v0 = fmaxf(v0, 0.f); v1 = fmaxf(v1, 0.f);
                v2 = fmaxf(v2, 0.f); v3 = fmaxf(v3, 0.f);
            }
            if (HALF_OUT) {
                __half* C = (__half*)Cout;
                if (row0 < M)
                    *(__half2*)(C + (size_t)row0 * 256 + col) = __floats2half2_rn(v0, v1);
                if (row1 < M)
                    *(__half2*)(C + (size_t)row1 * 256 + col) = __floats2half2_rn(v2, v3);
            } else {
                float* C = (float*)Cout;
                if (row0 < M)
                    *(float2*)(C + (size_t)row0 * 256 + col) = make_float2(v0 * mk0, v1 * mk0);
                if (row1 < M)
                    *(float2*)(C + (size_t)row1 * 256 + col) = make_float2(v2 * mk1, v3 * mk1);
            }
        }
    }
}

// ---------------- global mean pool (batch sorted): block per graph ----------
__global__ void __launch_bounds__(256)
k_pool2(const int* __restrict__ batch, const __half* __restrict__ h) {
    int gph = blockIdx.x;
    __shared__ int s_lo, s_hi;
    if (threadIdx.x == 0) {
        int lo = 0, hi = NN;
        while (lo < hi) { int mid = (lo + hi) >> 1; if (batch[mid] < gph) lo = mid + 1; else hi = mid; }
        s_lo = lo;
    }
    if (threadIdx.x == 1) {
        int lo = 0, hi = NN;
        while (lo < hi) { int mid = (lo + hi) >> 1; if (batch[mid] < gph + 1) lo = mid + 1; else hi = mid; }
        s_hi = lo;
    }
    __syncthreads();
    int lo = s_lo, hi = s_hi;
    float acc = 0.f;
    for (int v = lo; v < hi; v++)
        acc += __half2float(h[(size_t)v * 256 + threadIdx.x]);
    g_poolh[(size_t)gph * 256 + threadIdx.x] =
        __float2half(acc / fmaxf((float)(hi - lo), 1.f));
    if (threadIdx.x == 0) g_maskf[gph] = (hi > lo) ? 1.f : 0.f;
}

// ---------------- launch ----------------------------------------------------
extern "C" void kernel_launch(void* const* d_in, const int* in_sizes, int n_in,
                              void* d_out, int out_size) {
    const float* x     = (const float*)d_in[0];
    const float* W1    = (const float*)d_in[1];
    const float* b1    = (const float*)d_in[2];
    const float* W2    = (const float*)d_in[3];
    const float* b2    = (const float*)d_in[4];
    const float* W3    = (const float*)d_in[5];
    const float* b3    = (const float*)d_in[6];
    const int*   ei    = (const int*)d_in[7];
    const int*   batch = (const int*)d_in[8];
    float*       out   = (float*)d_out;

    __half *hA, *hB, *xh, *w1h, *w2h, *w3h, *poolh;
    float  *maskb;
    cudaGetSymbolAddress((void**)&hA,    g_bufAh);
    cudaGetSymbolAddress((void**)&hB,    g_bufBh);
    cudaGetSymbolAddress((void**)&xh,    g_xh);
    cudaGetSymbolAddress((void**)&w1h,   g_w1h);
    cudaGetSymbolAddress((void**)&w2h,   g_w2h);
    cudaGetSymbolAddress((void**)&w3h,   g_w3h);
    cudaGetSymbolAddress((void**)&poolh, g_poolh);
    cudaGetSymbolAddress((void**)&maskb, g_maskf);

    dim3 blk(256);
    int gN = (NN + 255) / 256;
    int gE = (EE + 255) / 256;

    // conversions + CSR build
    k_cvt_w<<<(256 * IN_DIM + 255) / 256, blk>>>(W1, w1h, IN_DIM);
    k_cvt_w<<<(256 * HID + 255) / 256, blk>>>(W2, w2h, HID);
    k_cvt_w<<<(256 * HID + 255) / 256, blk>>>(W3, w3h, HID);
    k_cvt_x<<<(NN * IN_DIM / 4 + 255) / 256, blk>>>(x);
    k_hist<<<gE, blk>>>(ei);
    k_scan1<<<NB_SCAN, SCAN_BLK>>>();
    k_scan2<<<1, 32>>>();
    k_scan3<<<gN, blk>>>();
    k_fill<<<gE, blk>>>(ei);

    dim3 ggrid(2, (NN + 127) / 128);
    dim3 ggrid3(2, GG / 128);
    int gAgg = (NN * 32 + 255) / 256;

    // layer 1: agg in 128-dim (half), GEMM(+bias+relu) -> half
    k_agg_h<128><<<gAgg, 256>>>(xh, hA);
    k_gemm_h<true, false, true><<<ggrid, 256>>>(hA, w1h, b1, nullptr, hB, NN, IN_DIM);

    // layer 2
    k_agg_h<256><<<gAgg, 256>>>(hB, hA);
    k_gemm_h<true, false, true><<<ggrid, 256>>>(hA, w2h, b2, nullptr, hB, NN, HID);

    // layer 3: agg, pool (linear), tiny GEMM on pooled [G,256] -> float out
    k_agg_h<256><<<gAgg, 256>>>(hB, hA);
    k_pool2<<<GG, 256>>>(batch, hA);
    k_gemm_h<false, true, false><<<ggrid3, 256>>>(poolh, w3h, b3, maskb, out, GG, HID);
}

// round 7
// speedup vs baseline: 3.8960x; 1.0973x over previous
#include <cuda_runtime.h>
#include <cuda_fp16.h>
#include <math.h>
#include <stdint.h>

#define NN      100000
#define EE      800000
#define IN_DIM  128
#define HID     256
#define OUT_DIM 256
#define GG      2048

#define SCAN_BLK 1024
#define NB_SCAN  ((NN + SCAN_BLK - 1) / SCAN_BLK)   // 98

// fused prep kernel ranges
#define XQ      (NN * IN_DIM / 4)           // 3,200,000 x-quads
#define W1E     (256 * IN_DIM)              // 32768
#define W2E     (256 * HID)                 // 65536
#define W3E     (256 * HID)                 // 65536
#define PREP_T  (XQ + W1E + W2E + W3E + EE) // total threads

// ---------------- scratch (device globals; no allocation allowed) -----------
__device__ __half g_bufAh[(size_t)NN * HID];
__device__ __half g_bufBh[(size_t)NN * HID];
__device__ __half g_xh[(size_t)NN * IN_DIM];
__device__ __half g_w1h[256 * IN_DIM];    // [n][k] transposed
__device__ __half g_w2h[256 * HID];
__device__ __half g_w3h[256 * HID];
__device__ __half g_poolh[(size_t)GG * OUT_DIM];
__device__ float  g_dis[NN];
__device__ int    g_deg[NN];         // zero-init at load; re-zeroed in k_fill
__device__ int    g_rowptr[NN + 1];
__device__ int    g_cursor[NN];
__device__ int    g_csrc[EE];
__device__ float  g_cnorm[EE];
__device__ int    g_bsum[NB_SCAN];
__device__ float  g_maskf[GG];

// ---------------- helpers ---------------------------------------------------
__device__ __forceinline__ uint32_t smem_u32(const void* p) {
    uint32_t a;
    asm("{ .reg .u64 t; cvta.to.shared.u64 t, %1; cvt.u32.u64 %0, t; }"
        : "=r"(a) : "l"(p));
    return a;
}

__device__ __forceinline__ void cp16(uint32_t dst, const void* src, int src_sz) {
    asm volatile("cp.async.cg.shared.global [%0], [%1], 16, %2;"
                 :: "r"(dst), "l"(src), "r"(src_sz));
}

__device__ __forceinline__ void mma_f16(float* c, const uint32_t* a, const uint32_t* b) {
    asm volatile(
        "mma.sync.aligned.m16n8k16.row.col.f32.f16.f16.f32 "
        "{%0,%1,%2,%3}, {%4,%5,%6,%7}, {%8,%9}, {%0,%1,%2,%3};"
        : "+f"(c[0]), "+f"(c[1]), "+f"(c[2]), "+f"(c[3])
        : "r"(a[0]), "r"(a[1]), "r"(a[2]), "r"(a[3]), "r"(b[0]), "r"(b[1]));
}

__device__ __forceinline__ void ldmx4(uint32_t* r, uint32_t addr) {
    asm volatile("ldmatrix.sync.aligned.m8n8.x4.shared.b16 {%0,%1,%2,%3}, [%4];"
                 : "=r"(r[0]), "=r"(r[1]), "=r"(r[2]), "=r"(r[3]) : "r"(addr));
}

// ---------------- fused prep: cvt x + 3 weight transposes + degree hist -----
// edge_index / batch arrive as INT32 (JAX x64-disabled)
__global__ void k_prep(const float* __restrict__ x,
                       const float* __restrict__ W1,
                       const float* __restrict__ W2,
                       const float* __restrict__ W3,
                       const int* __restrict__ ei) {
    int i = blockIdx.x * blockDim.x + threadIdx.x;
    if (i < XQ) {
        float4 v = ((const float4*)x)[i];
        __half2 h0 = __floats2half2_rn(v.x, v.y);
        __half2 h1 = __floats2half2_rn(v.z, v.w);
        uint2 u;
        u.x = *(uint32_t*)&h0;
        u.y = *(uint32_t*)&h1;
        ((uint2*)g_xh)[i] = u;
    } else if (i < XQ + W1E) {
        int j = i - XQ;
        int n = j >> 7, k = j & 127;
        g_w1h[j] = __float2half(W1[(size_t)k * 256 + n]);
    } else if (i < XQ + W1E + W2E) {
        int j = i - XQ - W1E;
        int n = j >> 8, k = j & 255;
        g_w2h[j] = __float2half(W2[(size_t)k * 256 + n]);
    } else if (i < XQ + W1E + W2E + W3E) {
        int j = i - XQ - W1E - W2E;
        int n = j >> 8, k = j & 255;
        g_w3h[j] = __float2half(W3[(size_t)k * 256 + n]);
    } else if (i < PREP_T) {
        int e = i - XQ - W1E - W2E - W3E;
        atomicAdd(&g_deg[ei[EE + e]], 1);
    }
}

// ---------------- graph-structure kernels -----------------------------------
__global__ void k_scan1() {
    __shared__ int s[SCAN_BLK];
    int tid = threadIdx.x;
    int i = blockIdx.x * SCAN_BLK + tid;
    int v = 0;
    if (i < NN) {
        v = g_deg[i];
        g_dis[i] = rsqrtf((float)(v + 1));   // +1 self loop
    }
    s[tid] = v;
    __syncthreads();
    for (int off = 1; off < SCAN_BLK; off <<= 1) {
        int t = (tid >= off) ? s[tid - off] : 0;
        __syncthreads();
        s[tid] += t;
        __syncthreads();
    }
    if (i < NN) g_rowptr[i] = s[tid] - v;
    if (tid == SCAN_BLK - 1) g_bsum[blockIdx.x] = s[tid];
}

__global__ void k_scan2() {
    if (threadIdx.x == 0) {
        int acc = 0;
        for (int b = 0; b < NB_SCAN; b++) {
            int t = g_bsum[b];
            g_bsum[b] = acc;
            acc += t;
        }
    }
}

__global__ void k_scan3() {
    int i = blockIdx.x * blockDim.x + threadIdx.x;
    if (i < NN) {
        int r = g_rowptr[i] + g_bsum[i / SCAN_BLK];
        g_rowptr[i] = r;
        g_cursor[i] = r;
    }
    if (i == 0) g_rowptr[NN] = EE;
}

__global__ void k_fill(const int* __restrict__ ei) {
    int e = blockIdx.x * blockDim.x + threadIdx.x;
    if (e < EE) {
        int s = ei[e];
        int d = ei[EE + e];
        int p = atomicAdd(&g_cursor[d], 1);
        g_csrc[p]  = s;
        g_cnorm[p] = g_dis[s] * g_dis[d];
    }
    if (e < NN) g_deg[e] = 0;   // re-zero for next graph replay
}

// ---------------- aggregation: warp per node, half gather, fp32 accum -------
template <int D>   // D in {128, 256}
__global__ void __launch_bounds__(256)
k_agg_h(const __half* __restrict__ in, __half* __restrict__ out) {
    constexpr int VH = D / 64;            // half2 per lane: 2 or 4
    int v    = (blockIdx.x * 256 + threadIdx.x) >> 5;
    int lane = threadIdx.x & 31;
    if (v >= NN) return;

    float ds = g_dis[v];
    float ws = ds * ds;                   // self-loop weight

    const __half* rowv = in + (size_t)v * D + lane * (VH * 2);
    float2 a[VH];
#pragma unroll
    for (int j = 0; j < VH; j++) {
        float2 x = __half22float2(((const __half2*)rowv)[j]);
        a[j] = make_float2(ws * x.x, ws * x.y);
    }

    int beg = g_rowptr[v];
    int end = g_rowptr[v + 1];
    int cnt = end - beg;
    int i = beg;
    int end4 = beg + (cnt & ~3);
    for (; i < end4; i += 4) {
        int   sv[4];
        float nv[4];
        __half2 h[4][VH];
#pragma unroll
        for (int q = 0; q < 4; q++) { sv[q] = g_csrc[i + q]; nv[q] = g_cnorm[i + q]; }
#pragma unroll
        for (int q = 0; q < 4; q++) {
            const __half2* r = (const __half2*)(in + (size_t)sv[q] * D + lane * (VH * 2));
            if (VH == 4) {
                float4 u = *(const float4*)r;
                h[q][0] = *(__half2*)&u.x; h[q][1] = *(__half2*)&u.y;
                h[q][2] = *(__half2*)&u.z; h[q][3] = *(__half2*)&u.w;
            } else {
                float2 u = *(const float2*)r;
                h[q][0] = *(__half2*)&u.x; h[q][1] = *(__half2*)&u.y;
            }
        }
#pragma unroll
        for (int q = 0; q < 4; q++)
#pragma unroll
            for (int j = 0; j < VH; j++) {
                float2 y = __half22float2(h[q][j]);
                a[j].x += nv[q] * y.x;
                a[j].y += nv[q] * y.y;
            }
    }
    for (; i < end; i++) {
        int   s0 = g_csrc[i];
        float n0 = g_cnorm[i];
        const __half2* r0 = (const __half2*)(in + (size_t)s0 * D + lane * (VH * 2));
#pragma unroll
        for (int j = 0; j < VH; j++) {
            float2 y0 = __half22float2(r0[j]);
            a[j].x += n0 * y0.x;
            a[j].y += n0 * y0.y;
        }
    }

    __half2* o = (__half2*)(out + (size_t)v * D + lane * (VH * 2));
#pragma unroll
    for (int j = 0; j < VH; j++)
        o[j] = __floats2half2_rn(a[j].x, a[j].y);
}

// ---------------- fp16 tensor-core GEMM, cp.async + ldmatrix ----------------
// C[M,256] = act(A[M,K] @ Wt^T + bias) [* mask[row]]
// A: [M][K] half (row-major). Wt: [256][K] half (n-major).
template <bool RELU, bool MASK, bool HALF_OUT>
__global__ void __launch_bounds__(256, 2)
k_gemm_h(const __half* __restrict__ A, const __half* __restrict__ Wt,
         const float* __restrict__ bias, const float* __restrict__ mask,
         void* __restrict__ Cout, int M, int K) {
    __shared__ __half As[2][128][40];   // [m][k], 80B rows -> conflict-free
    __shared__ __half Bs[2][128][40];   // [n][k]

    int tid  = threadIdx.x;
    int wid  = tid >> 5;
    int lane = tid & 31;
    int g    = lane >> 2;           // 0..7
    int tig  = lane & 3;            // 0..3
    int warp_m = wid & 1;
    int warp_n = wid >> 1;
    int brow = blockIdx.y * 128;
    int bcol = blockIdx.x * 128;

    float acc[4][4][4];
#pragma unroll
    for (int i = 0; i < 4; i++)
#pragma unroll
        for (int j = 0; j < 4; j++)
#pragma unroll
            for (int l = 0; l < 4; l++) acc[i][j][l] = 0.f;

    int lr  = tid >> 2;             // 0..63 (+64 on l=1)
    int lc8 = (tid & 3) << 3;       // k-offset 0,8,16,24 halves

    auto load_tiles = [&](int s, int k0) {
#pragma unroll
        for (int l = 0; l < 2; l++) {
            int r = lr + l * 64;
            int row = brow + r;
            cp16(smem_u32(&As[s][r][lc8]),
                 A + (size_t)row * K + k0 + lc8, row < M ? 16 : 0);
            cp16(smem_u32(&Bs[s][r][lc8]),
                 Wt + (size_t)(bcol + r) * K + k0 + lc8, 16);
        }
        asm volatile("cp.async.commit_group;");
    };

    // ldmatrix per-lane address components
    int a_r  = lane & 15;           // row within 16-row frag
    int a_c8 = (lane & 16) >> 1;    // +8 cols for upper half
    int b_r  = ((lane & 16) >> 1) + (lane & 7);  // n within 16-row pair
    int b_c8 = lane & 8;            // +8 cols

    load_tiles(0, 0);
    int s = 0;
    for (int k0 = 0; k0 < K; k0 += 32) {
        if (k0 + 32 < K) load_tiles(s ^ 1, k0 + 32);
        else             asm volatile("cp.async.commit_group;");
        asm volatile("cp.async.wait_group 1;");
        __syncthreads();

#pragma unroll
        for (int ks = 0; ks < 32; ks += 16) {
            uint32_t af[4][4], bf[4][2];
#pragma unroll
            for (int mf = 0; mf < 4; mf++) {
                int m0 = warp_m * 64 + mf * 16;
                ldmx4(af[mf], smem_u32(&As[s][m0 + a_r][ks + a_c8]));
            }
#pragma unroll
            for (int p = 0; p < 2; p++) {
                int n0 = warp_n * 32 + p * 16;
                uint32_t br[4];
                ldmx4(br, smem_u32(&Bs[s][n0 + b_r][ks + b_c8]));
                bf[2 * p][0] = br[0]; bf[2 * p][1] = br[1];
                bf[2 * p + 1][0] = br[2]; bf[2 * p + 1][1] = br[3];
            }
#pragma unroll
            for (int mf = 0; mf < 4; mf++)
#pragma unroll
                for (int nf = 0; nf < 4; nf++)
                    mma_f16(acc[mf][nf], af[mf], bf[nf]);
        }
        __syncthreads();
        s ^= 1;
    }

#pragma unroll
    for (int mf = 0; mf < 4; mf++) {
        int row0 = brow + warp_m * 64 + mf * 16 + g;
        int row1 = row0 + 8;
        float mk0 = 1.f, mk1 = 1.f;
        if (MASK) {
            if (row0 < M) mk0 = mask[row0];
            if (row1 < M) mk1 = mask[row1];
        }
#pragma unroll
        for (int nf = 0; nf < 4; nf++) {
            int col = bcol + warp_n * 32 + nf * 8 + tig * 2;
            float2 bb = *(const float2*)(bias + col);
            float v0 = acc[mf][nf][0] + bb.x;
            float v1 = acc[mf][nf][1] + bb.y;
            float v2 = acc[mf][nf][2] + bb.x;
            float v3 = acc[mf][nf][3] + bb.y;
            if (RELU) {
                v0 = fmaxf(v0, 0.f); v1 = fmaxf(v1, 0.f);
                v2 = fmaxf(v2, 0.f); v3 = fmaxf(v3, 0.f);
            }
            if (HALF_OUT) {
                __half* C = (__half*)Cout;
                if (row0 < M)
                    *(__half2*)(C + (size_t)row0 * 256 + col) = __floats2half2_rn(v0, v1);
                if (row1 < M)
                    *(__half2*)(C + (size_t)row1 * 256 + col) = __floats2half2_rn(v2, v3);
            } else {
                float* C = (float*)Cout;
                if (row0 < M)
                    *(float2*)(C + (size_t)row0 * 256 + col) = make_float2(v0 * mk0, v1 * mk0);
                if (row1 < M)
                    *(float2*)(C + (size_t)row1 * 256 + col) = make_float2(v2 * mk1, v3 * mk1);
            }
        }
    }
}

// ---------------- global mean pool (batch sorted): block per graph ----------
__global__ void __launch_bounds__(256)
k_pool2(const int* __restrict__ batch, const __half* __restrict__ h) {
    int gph = blockIdx.x;
    __shared__ int s_lo, s_hi;
    if (threadIdx.x == 0) {
        int lo = 0, hi = NN;
        while (lo < hi) { int mid = (lo + hi) >> 1; if (batch[mid] < gph) lo = mid + 1; else hi = mid; }
        s_lo = lo;
    }
    if (threadIdx.x == 1) {
        int lo = 0, hi = NN;
        while (lo < hi) { int mid = (lo + hi) >> 1; if (batch[mid] < gph + 1) lo = mid + 1; else hi = mid; }
        s_hi = lo;
    }
    __syncthreads();
    int lo = s_lo, hi = s_hi;
    float acc = 0.f;
    for (int v = lo; v < hi; v++)
        acc += __half2float(h[(size_t)v * 256 + threadIdx.x]);
    g_poolh[(size_t)gph * 256 + threadIdx.x] =
        __float2half(acc / fmaxf((float)(hi - lo), 1.f));
    if (threadIdx.x == 0) g_maskf[gph] = (hi > lo) ? 1.f : 0.f;
}

// ---------------- launch ----------------------------------------------------
extern "C" void kernel_launch(void* const* d_in, const int* in_sizes, int n_in,
                              void* d_out, int out_size) {
    const float* x     = (const float*)d_in[0];
    const float* W1    = (const float*)d_in[1];
    const float* b1    = (const float*)d_in[2];
    const float* W2    = (const float*)d_in[3];
    const float* b2    = (const float*)d_in[4];
    const float* W3    = (const float*)d_in[5];
    const float* b3    = (const float*)d_in[6];
    const int*   ei    = (const int*)d_in[7];
    const int*   batch = (const int*)d_in[8];
    float*       out   = (float*)d_out;

    __half *hA, *hB, *xh, *w1h, *w2h, *w3h, *poolh;
    float  *maskb;
    cudaGetSymbolAddress((void**)&hA,    g_bufAh);
    cudaGetSymbolAddress((void**)&hB,    g_bufBh);
    cudaGetSymbolAddress((void**)&xh,    g_xh);
    cudaGetSymbolAddress((void**)&w1h,   g_w1h);
    cudaGetSymbolAddress((void**)&w2h,   g_w2h);
    cudaGetSymbolAddress((void**)&w3h,   g_w3h);
    cudaGetSymbolAddress((void**)&poolh, g_poolh);
    cudaGetSymbolAddress((void**)&maskb, g_maskf);

    dim3 blk(256);
    int gN = (NN + 255) / 256;
    int gE = (EE + 255) / 256;

    // fused prep (cvt x, transpose+cvt weights, degree hist) + CSR build
    k_prep<<<(PREP_T + 255) / 256, blk>>>(x, W1, W2, W3, ei);
    k_scan1<<<NB_SCAN, SCAN_BLK>>>();
    k_scan2<<<1, 32>>>();
    k_scan3<<<gN, blk>>>();
    k_fill<<<gE, blk>>>(ei);

    dim3 ggrid(2, (NN + 127) / 128);
    dim3 ggrid3(2, GG / 128);
    int gAgg = (NN * 32 + 255) / 256;

    // layer 1: agg in 128-dim (half), GEMM(+bias+relu) -> half
    k_agg_h<128><<<gAgg, 256>>>(xh, hA);
    k_gemm_h<true, false, true><<<ggrid, 256>>>(hA, w1h, b1, nullptr, hB, NN, IN_DIM);

    // layer 2
    k_agg_h<256><<<gAgg, 256>>>(hB, hA);
    k_gemm_h<true, false, true><<<ggrid, 256>>>(hA, w2h, b2, nullptr, hB, NN, HID);

    // layer 3: agg, pool (linear), tiny GEMM on pooled [G,256] -> float out
    k_agg_h<256><<<gAgg, 256>>>(hB, hA);
    k_pool2<<<GG, 256>>>(batch, hA);
    k_gemm_h<false, true, false><<<ggrid3, 256>>>(poolh, w3h, b3, maskb, out, GG, HID);
}